// round 14
// baseline (speedup 1.0000x reference)
#include <cuda_runtime.h>
#include <cuda_fp16.h>
#include <cstdint>
#include <math.h>

#define LSEQ 2048
#define NDIM 512
#define NHEAD 8
#define HDIM 64
#define QSD 1024
#define FD 128
#define PI_F 3.14159265358979323846f
#define CSC (1024.0f / 1023.0f)

// ---------------- static device scratch ----------------
__device__ __align__(256) float  g_qs[LSEQ * QSD];
__device__ __align__(256) __half g_qf[NHEAD * LSEQ * FD];
__device__ __align__(256) __half g_kf[NHEAD * LSEQ * FD];
__device__ __align__(256) __half g_v [NHEAD * LSEQ * HDIM];
__device__ __align__(256) __half g_xh[LSEQ * NDIM];
__device__ __align__(256) __half g_w1h[NDIM * QSD];   // W_qs K-major hi
__device__ __align__(256) __half g_woh[NDIM * NDIM];  // W_out K-major hi
__device__ __align__(256) __half g_wol[NDIM * NDIM];
__device__ __align__(256) __half g_aoh[LSEQ * NDIM];

// ---------------- asm helpers ----------------
__device__ __forceinline__ uint32_t smem_u32(const void* p) {
    return (uint32_t)__cvta_generic_to_shared(p);
}
__device__ __forceinline__ void ldsm_x4(uint32_t r[4], uint32_t addr) {
    asm volatile("ldmatrix.sync.aligned.m8n8.x4.shared.b16 {%0,%1,%2,%3}, [%4];"
        : "=r"(r[0]), "=r"(r[1]), "=r"(r[2]), "=r"(r[3]) : "r"(addr));
}
__device__ __forceinline__ void ldsm_x4_t(uint32_t r[4], uint32_t addr) {
    asm volatile("ldmatrix.sync.aligned.m8n8.x4.trans.shared.b16 {%0,%1,%2,%3}, [%4];"
        : "=r"(r[0]), "=r"(r[1]), "=r"(r[2]), "=r"(r[3]) : "r"(addr));
}
__device__ __forceinline__ void mma16816(float c[4], const uint32_t a0, const uint32_t a1,
                                         const uint32_t a2, const uint32_t a3,
                                         const uint32_t b0, const uint32_t b1) {
    asm volatile("mma.sync.aligned.m16n8k16.row.col.f32.f16.f16.f32 "
        "{%0,%1,%2,%3}, {%4,%5,%6,%7}, {%8,%9}, {%0,%1,%2,%3};"
        : "+f"(c[0]), "+f"(c[1]), "+f"(c[2]), "+f"(c[3])
        : "r"(a0), "r"(a1), "r"(a2), "r"(a3), "r"(b0), "r"(b1));
}
__device__ __forceinline__ uint32_t pack_h2(float x, float y) {
    __half2 h = __floats2half2_rn(x, y);
    return *reinterpret_cast<uint32_t*>(&h);
}
__device__ __forceinline__ void cp16(uint32_t dst, const void* src) {
    asm volatile("cp.async.cg.shared.global [%0], [%1], 16;" :: "r"(dst), "l"(src));
}
__device__ __forceinline__ void cp_commit() { asm volatile("cp.async.commit_group;"); }
__device__ __forceinline__ void cp_wait1()  { asm volatile("cp.async.wait_group 1;"); }
__device__ __forceinline__ void cp_wait0()  { asm volatile("cp.async.wait_group 0;"); }

// exp(s * 0.125) for |s| <= ~1.05 via cubic Horner (coeffs absorb the /8).
__device__ __forceinline__ float exp8(float s) {
    float p = fmaf(s, 3.2552083e-4f, 0.0078125f);
    p = fmaf(p, s, 0.125f);
    return fmaf(p, s, 1.0f);
}

// ---------------- merged split prep ----------------
__global__ __launch_bounds__(256)
void prep_kernel(const float* __restrict__ x, const float* __restrict__ W_qs,
                 const float* __restrict__ W_out)
{
    const int NX = LSEQ * NDIM;
    const int NW1 = NDIM * QSD;
    const int NWO = NDIM * NDIM;
    int i = blockIdx.x * 256 + threadIdx.x;
    if (i < NX) {
        g_xh[i] = __float2half_rn(x[i]);
    } else if (i < NX + NW1) {
        int j = i - NX;
        g_w1h[j] = __float2half_rn(W_qs[j]);
    } else if (i < NX + NW1 + NWO) {
        int j = i - NX - NW1;
        float v = W_out[j];
        __half h = __float2half_rn(v);
        g_woh[j] = h;
        g_wol[j] = __float2half_rn(v - __half2float(h));
    }
}

// ---------------- HMMA GEMM: 3-stage cp.async, single barrier per K-tile ----------------
#define GLD 72
#define BSTR 72

template<int NTERMS>
__global__ __launch_bounds__(128)
void hmma_gemm(const __half* __restrict__ Ah,
               const __half* __restrict__ Bh, const __half* __restrict__ Bl,
               const float* __restrict__ bias, float* __restrict__ C,
               int N, int K)
{
    extern __shared__ __half gsm[];
    const uint32_t sbase = smem_u32(gsm);

    constexpr int A_SZ  = 128 * GLD;
    constexpr int ST_AH = 0;
    constexpr int ST_BH = A_SZ;
    constexpr int ST_BL = A_SZ + 64 * BSTR;
    constexpr int STAGE = A_SZ + (NTERMS >= 2 ? 2 : 1) * 64 * BSTR;

    const int tid  = threadIdx.x;
    const int warp = tid >> 5;
    const int lane = tid & 31;
    const int m0 = blockIdx.y << 7, n0 = blockIdx.x << 6;
    const int KT = K >> 6;

    float acc[2][8][4] = {};

    auto load_stage = [&](int st, int k0) {
        uint32_t sb = sbase + st * STAGE * 2;
        #pragma unroll 4
        for (int i = tid; i < 128 * 8; i += 128) {
            int r = i >> 3, c = (i & 7) << 3;
            cp16(sb + (ST_AH + r * GLD + c) * 2, Ah + (size_t)(m0 + r) * K + k0 + c);
        }
        #pragma unroll 4
        for (int i = tid; i < 64 * 8; i += 128) {
            int r = i >> 3, c = (i & 7) << 3;
            cp16(sb + (ST_BH + r * BSTR + c) * 2, Bh + (size_t)(k0 + r) * N + n0 + c);
            if (NTERMS >= 2)
                cp16(sb + (ST_BL + r * BSTR + c) * 2, Bl + (size_t)(k0 + r) * N + n0 + c);
        }
    };

    // preload tiles 0,1 into stages 0,1
    load_stage(0, 0);
    cp_commit();
    if (KT > 1) { load_stage(1, 64); }
    cp_commit();   // commit (possibly empty) group so counts stay uniform

    for (int t = 0; t < KT; ++t) {
        if (t + 1 < KT) cp_wait1(); else cp_wait0();
        __syncthreads();
        if (t + 2 < KT) { load_stage((t + 2) % 3, (t + 2) << 6); }
        cp_commit();

        const uint32_t sb = sbase + (t % 3) * STAGE * 2;

        #pragma unroll
        for (int sp2 = 0; sp2 < 2; ++sp2) {
            uint32_t ah[2][2][4];
            #pragma unroll
            for (int rb = 0; rb < 2; ++rb) {
                int abase = (warp * 32 + rb * 16 + (lane & 15)) * GLD
                            + sp2 * 32 + ((lane >> 4) << 3);
                ldsm_x4(ah[rb][0], sb + (ST_AH + abase) * 2);
                ldsm_x4(ah[rb][1], sb + (ST_AH + abase + 16) * 2);
            }
            const int brow = sp2 * 32 + ((lane >> 3) << 3) + (lane & 7);
            #pragma unroll
            for (int nt = 0; nt < 8; ++nt) {
                uint32_t bh[4], bl[4];
                ldsm_x4_t(bh, sb + (ST_BH + brow * BSTR + nt * 8) * 2);
                if (NTERMS >= 2)
                    ldsm_x4_t(bl, sb + (ST_BL + brow * BSTR + nt * 8) * 2);
                #pragma unroll
                for (int rb = 0; rb < 2; ++rb) {
                    mma16816(acc[rb][nt], ah[rb][0][0], ah[rb][0][1], ah[rb][0][2], ah[rb][0][3], bh[0], bh[1]);
                    mma16816(acc[rb][nt], ah[rb][1][0], ah[rb][1][1], ah[rb][1][2], ah[rb][1][3], bh[2], bh[3]);
                    if (NTERMS >= 2) {
                        mma16816(acc[rb][nt], ah[rb][0][0], ah[rb][0][1], ah[rb][0][2], ah[rb][0][3], bl[0], bl[1]);
                        mma16816(acc[rb][nt], ah[rb][1][0], ah[rb][1][1], ah[rb][1][2], ah[rb][1][3], bl[2], bl[3]);
                    }
                }
            }
        }
    }

    const int g   = lane >> 2;
    const int tig = lane & 3;
    #pragma unroll
    for (int rb = 0; rb < 2; ++rb) {
        int row0 = m0 + warp * 32 + rb * 16 + g;
        #pragma unroll
        for (int nt = 0; nt < 8; ++nt) {
            int col = n0 + nt * 8 + tig * 2;
            C[(size_t)row0 * N + col]           = acc[rb][nt][0] + bias[col];
            C[(size_t)row0 * N + col + 1]       = acc[rb][nt][1] + bias[col + 1];
            C[(size_t)(row0 + 8) * N + col]     = acc[rb][nt][2] + bias[col];
            C[(size_t)(row0 + 8) * N + col + 1] = acc[rb][nt][3] + bias[col + 1];
        }
    }
}

// ---------------- LN + activations + features (R13-proven) ----------------
__global__ __launch_bounds__(256)
void ln_feat_kernel(const float* __restrict__ x,
                    const float* __restrict__ ln_w, const float* __restrict__ ln_b,
                    const float* __restrict__ freq, const float* __restrict__ shift)
{
    const int i = blockIdx.x;
    const int tid = threadIdx.x;
    const int lane = tid & 31, warp = tid >> 5;
    __shared__ float sh[QSD];
    __shared__ float redA[8], redB[8];
    __shared__ float bcast[2];

    float4 v = reinterpret_cast<const float4*>(g_qs + (size_t)i * QSD)[tid];
    reinterpret_cast<float4*>(sh)[tid] = v;
    float s  = v.x + v.y + v.z + v.w;
    float s2 = v.x * v.x + v.y * v.y + v.z * v.z + v.w * v.w;
    #pragma unroll
    for (int o = 16; o; o >>= 1) {
        s  += __shfl_xor_sync(0xffffffffu, s, o);
        s2 += __shfl_xor_sync(0xffffffffu, s2, o);
    }
    if (!lane) { redA[warp] = s; redB[warp] = s2; }
    __syncthreads();
    if (tid == 0) {
        float a = 0.f, b = 0.f;
        #pragma unroll
        for (int w = 0; w < 8; ++w) { a += redA[w]; b += redB[w]; }
        float mean = a * (1.0f / QSD);
        float var  = b * (1.0f / QSD) - mean * mean;
        bcast[0] = mean;
        bcast[1] = rsqrtf(var + 1e-5f);
    }
    __syncthreads();
    const float mean = bcast[0], rstd = bcast[1];

    float a0, a1;
    {
        float2 ap = reinterpret_cast<const float2*>(sh)[tid];
        float2 w  = reinterpret_cast<const float2*>(ln_w)[tid];
        float2 b  = reinterpret_cast<const float2*>(ln_b)[tid];
        float n0 = (ap.x - mean) * rstd * w.x + b.x;
        float n1 = (ap.y - mean) * rstd * w.y + b.y;
        a0 = 1.0f / (1.0f + __expf(-n0));
        a1 = 1.0f / (1.0f + __expf(-n1));
    }
    float sa2 = a0 * a0 + a1 * a1;
    #pragma unroll
    for (int o = 16; o; o >>= 1) sa2 += __shfl_xor_sync(0xffffffffu, sa2, o);
    if (!lane) redA[warp] = sa2;
    __syncthreads();
    if (tid == 0) {
        float t = 0.f;
        #pragma unroll
        for (int w = 0; w < 8; ++w) t += redA[w];
        bcast[0] = 1.0f / (sqrtf(t) + 1e-8f);
    }
    __syncthreads();
    const float rnorm = bcast[0];

    float2 pp = reinterpret_cast<const float2*>(sh + NDIM)[tid];
    float2 pw = reinterpret_cast<const float2*>(ln_w + NDIM)[tid];
    float2 pb = reinterpret_cast<const float2*>(ln_b + NDIM)[tid];
    float z0 = (pp.x - mean) * rstd * pw.x + pb.x;
    float z1 = (pp.y - mean) * rstd * pw.y + pb.y;
    float e0 = __expf(2.0f * z0), e1 = __expf(2.0f * z1);
    float qp0 = ((e0 - 1.0f) / (e0 + 1.0f)) * PI_F;
    float qp1 = ((e1 - 1.0f) / (e1 + 1.0f)) * PI_F;

    const int c0 = tid * 2;
    const int h = c0 >> 6, d = c0 & 63;
    const float f  = freq[h];
    const float sp = shift[h];
    const float qa0 = a0 * rnorm, qa1 = a1 * rnorm;

    float B0 = CSC * f * qp0, B1 = CSC * f * qp1;
    float A0 = B0 + CSC * sp, A1 = B1 + CSC * sp;
    float ca0, sa0, cb0, sb0, ca1, sa1, cb1, sb1;
    __sincosf(A0, &sa0, &ca0); __sincosf(B0, &sb0, &cb0);
    __sincosf(A1, &sa1, &ca1); __sincosf(B1, &sb1, &cb1);

    size_t base = ((size_t)(h * LSEQ + i)) * FD;
    *reinterpret_cast<__half2*>(&g_qf[base + d])      = __floats2half2_rn(qa0 * ca0, qa1 * ca1);
    *reinterpret_cast<__half2*>(&g_qf[base + 64 + d]) = __floats2half2_rn(qa0 * sa0, qa1 * sa1);
    *reinterpret_cast<__half2*>(&g_kf[base + d])      = __floats2half2_rn(qa0 * cb0, qa1 * cb1);
    *reinterpret_cast<__half2*>(&g_kf[base + 64 + d]) = __floats2half2_rn(qa0 * sb0, qa1 * sb1);

    float2 xv = reinterpret_cast<const float2*>(x + (size_t)i * NDIM)[tid];
    *reinterpret_cast<__half2*>(&g_v[((size_t)(h * LSEQ + i)) * HDIM + d]) =
        __floats2half2_rn(xv.x, xv.y);
}

// ---------------- attention: 3-stage cp.async, single barrier per tile ----------------
#define KLD 136
#define VLD 72
#define A_VOFF (64 * KLD)
#define A_STAGE_B ((64 * KLD + 64 * VLD) * 2)   // 26624 bytes per stage

__global__ __launch_bounds__(128, 2)
void attn_kernel()
{
    extern __shared__ __half asmem[];
    const uint32_t sbase = smem_u32(asmem);

    const int h  = blockIdx.y;
    const int q0 = blockIdx.x << 6;
    const int tid  = threadIdx.x;
    const int warp = tid >> 5;
    const int lane = tid & 31;

    auto load_tile = [&](int st, int k0) {
        uint32_t sb = sbase + st * A_STAGE_B;
        const __half* kg = g_kf + ((size_t)(h * LSEQ + k0)) * FD;
        const __half* vg = g_v  + ((size_t)(h * LSEQ + k0)) * HDIM;
        #pragma unroll 4
        for (int i = tid; i < 64 * 16; i += 128) {
            int r = i >> 4, c = (i & 15) << 3;
            cp16(sb + (r * KLD + c) * 2, kg + (size_t)r * FD + c);
        }
        #pragma unroll 2
        for (int i = tid; i < 64 * 8; i += 128) {
            int r = i >> 3, c = (i & 7) << 3;
            cp16(sb + (A_VOFF + r * VLD + c) * 2, vg + (size_t)r * HDIM + c);
        }
    };

    // preload K/V tiles 0,1 into stages 0,1 (async), stage Q into stage 2 meanwhile
    load_tile(0, 0);
    cp_commit();
    load_tile(1, 64);
    cp_commit();

    {
        __half* qs = asmem + 2 * (A_STAGE_B / 2);
        const __half* qg = g_qf + ((size_t)(h * LSEQ + q0)) * FD;
        for (int idx = tid; idx < 64 * 16; idx += 128) {
            int r = idx >> 4, c = (idx & 15) << 3;
            *reinterpret_cast<uint4*>(&qs[r * KLD + c]) =
                *reinterpret_cast<const uint4*>(&qg[(size_t)r * FD + c]);
        }
    }
    __syncthreads();

    uint32_t qf[8][4];
    {
        const uint32_t qbase = sbase + 2 * A_STAGE_B;
        int row = warp * 16 + (lane & 15);
        int cof = (lane >> 4) << 3;
        #pragma unroll
        for (int ks = 0; ks < 8; ++ks)
            ldsm_x4(qf[ks], qbase + (row * KLD + ks * 16 + cof) * 2);
    }
    // NOTE: no barrier needed here; the loop's first barrier (iter 0) orders
    // everyone's qf pulls before stage 2 is overwritten (first overwrite is
    // load_tile(2) issued after that barrier).

    float oacc[8][4] = {};
    float rl0 = 0.f, rl1 = 0.f;

    const int NT = LSEQ / 64;
    for (int kt = 0; kt < NT; ++kt) {
        if (kt + 1 < NT) cp_wait1(); else cp_wait0();
        __syncthreads();
        if (kt + 2 < NT) { load_tile((kt + 2) % 3, (kt + 2) << 6); }
        cp_commit();

        const uint32_t sb = sbase + (kt % 3) * A_STAGE_B;

        float sacc[8][4] = {};
        #pragma unroll
        for (int sp = 0; sp < 4; ++sp) {
            #pragma unroll
            for (int nt = 0; nt < 8; ++nt) {
                uint32_t kf[4];
                ldsm_x4(kf, sb + ((nt * 8 + (lane & 7)) * KLD
                                  + sp * 32 + ((lane >> 3) << 3)) * 2);
                mma16816(sacc[nt], qf[2 * sp][0], qf[2 * sp][1], qf[2 * sp][2], qf[2 * sp][3],
                         kf[0], kf[1]);
                mma16816(sacc[nt], qf[2 * sp + 1][0], qf[2 * sp + 1][1],
                         qf[2 * sp + 1][2], qf[2 * sp + 1][3], kf[2], kf[3]);
            }
        }

        uint32_t pf[8][2];
        #pragma unroll
        for (int nt = 0; nt < 8; ++nt) {
            float e0 = exp8(sacc[nt][0]);
            float e1 = exp8(sacc[nt][1]);
            float e2 = exp8(sacc[nt][2]);
            float e3 = exp8(sacc[nt][3]);
            rl0 += e0 + e1;
            rl1 += e2 + e3;
            pf[nt][0] = pack_h2(e0, e1);
            pf[nt][1] = pack_h2(e2, e3);
        }

        #pragma unroll
        for (int sp = 0; sp < 2; ++sp) {
            int vrow = sp * 32 + ((lane >> 3) << 3) + (lane & 7);
            #pragma unroll
            for (int nt = 0; nt < 8; ++nt) {
                uint32_t vf[4];
                ldsm_x4_t(vf, sb + (A_VOFF + vrow * VLD + nt * 8) * 2);
                mma16816(oacc[nt], pf[4 * sp][0], pf[4 * sp][1],
                         pf[4 * sp + 1][0], pf[4 * sp + 1][1], vf[0], vf[1]);
                mma16816(oacc[nt], pf[4 * sp + 2][0], pf[4 * sp + 2][1],
                         pf[4 * sp + 3][0], pf[4 * sp + 3][1], vf[2], vf[3]);
            }
        }
    }

    rl0 += __shfl_xor_sync(0xffffffffu, rl0, 1);
    rl0 += __shfl_xor_sync(0xffffffffu, rl0, 2);
    rl1 += __shfl_xor_sync(0xffffffffu, rl1, 1);
    rl1 += __shfl_xor_sync(0xffffffffu, rl1, 2);
    const float inv0 = 1.0f / rl0;
    const float inv1 = 1.0f / rl1;

    const int g   = lane >> 2;
    const int tig = lane & 3;
    const int row0 = q0 + warp * 16 + g;
    #pragma unroll
    for (int nt = 0; nt < 8; ++nt) {
        int col = h * HDIM + nt * 8 + tig * 2;
        *reinterpret_cast<__half2*>(&g_aoh[(size_t)row0 * NDIM + col]) =
            __floats2half2_rn(oacc[nt][0] * inv0, oacc[nt][1] * inv0);
        *reinterpret_cast<__half2*>(&g_aoh[(size_t)(row0 + 8) * NDIM + col]) =
            __floats2half2_rn(oacc[nt][2] * inv1, oacc[nt][3] * inv1);
    }
}

// ---------------- launch ----------------
extern "C" void kernel_launch(void* const* d_in, const int* in_sizes, int n_in,
                              void* d_out, int out_size)
{
    const float* x     = (const float*)d_in[0];
    const float* W_qs  = (const float*)d_in[1];
    const float* b_qs  = (const float*)d_in[2];
    const float* ln_w  = (const float*)d_in[3];
    const float* ln_b  = (const float*)d_in[4];
    const float* freq  = (const float*)d_in[5];
    const float* phs   = (const float*)d_in[6];
    const float* W_out = (const float*)d_in[7];
    const float* b_out = (const float*)d_in[8];
    float* out = (float*)d_out;

    void *p_qs, *p_xh, *p_w1h, *p_woh, *p_wol, *p_aoh;
    cudaGetSymbolAddress(&p_qs, g_qs);
    cudaGetSymbolAddress(&p_xh, g_xh);
    cudaGetSymbolAddress(&p_w1h, g_w1h);
    cudaGetSymbolAddress(&p_woh, g_woh); cudaGetSymbolAddress(&p_wol, g_wol);
    cudaGetSymbolAddress(&p_aoh, g_aoh);

    const int smem_g1 = 3 * (128 * GLD + 64 * BSTR) * 2;       // 82944
    const int smem_g2 = 3 * (128 * GLD + 2 * 64 * BSTR) * 2;   // 110592
    const int attn_smem = 3 * A_STAGE_B;                       // 79872
    cudaFuncSetAttribute(hmma_gemm<1>, cudaFuncAttributeMaxDynamicSharedMemorySize, smem_g1);
    cudaFuncSetAttribute(hmma_gemm<2>, cudaFuncAttributeMaxDynamicSharedMemorySize, smem_g2);
    cudaFuncSetAttribute(attn_kernel,  cudaFuncAttributeMaxDynamicSharedMemorySize, attn_smem);

    // 0) merged prep
    const int NPREP = LSEQ * NDIM + NDIM * QSD + NDIM * NDIM;
    prep_kernel<<<(NPREP + 255) / 256, 256>>>(x, W_qs, W_out);

    // 1) qs = x @ W_qs + b_qs (fp16)
    hmma_gemm<1><<<dim3(QSD / 64, LSEQ / 128), 128, smem_g1>>>(
        (const __half*)p_xh,
        (const __half*)p_w1h, nullptr,
        b_qs, (float*)p_qs, QSD, NDIM);
    // 2) LN + activations + features
    ln_feat_kernel<<<LSEQ, 256>>>(x, ln_w, ln_b, freq, phs);
    // 3) attention
    attn_kernel<<<dim3(LSEQ / 64, NHEAD), 128, attn_smem>>>();
    // 4) out = AO @ W_out + b_out (2-term)
    hmma_gemm<2><<<dim3(NDIM / 64, LSEQ / 128), 128, smem_g2>>>(
        (const __half*)p_aoh,
        (const __half*)p_woh, (const __half*)p_wol,
        b_out, out, NDIM, NDIM);
}

// round 15
// speedup vs baseline: 1.0489x; 1.0489x over previous
#include <cuda_runtime.h>
#include <cuda_fp16.h>
#include <cstdint>
#include <math.h>

#define LSEQ 2048
#define NDIM 512
#define NHEAD 8
#define HDIM 64
#define QSD 1024
#define FD 128
#define PI_F 3.14159265358979323846f
#define CSC (1024.0f / 1023.0f)

// ---------------- static device scratch ----------------
__device__ __align__(256) float  g_qs[LSEQ * QSD];
__device__ __align__(256) __half g_qf[NHEAD * LSEQ * FD];
__device__ __align__(256) __half g_kf[NHEAD * LSEQ * FD];
__device__ __align__(256) __half g_v [NHEAD * LSEQ * HDIM];
__device__ __align__(256) __half g_xh[LSEQ * NDIM];
__device__ __align__(256) __half g_w1h[NDIM * QSD];   // W_qs K-major hi
__device__ __align__(256) __half g_woh[NDIM * NDIM];  // W_out K-major hi
__device__ __align__(256) __half g_wol[NDIM * NDIM];
__device__ __align__(256) __half g_aoh[LSEQ * NDIM];

// ---------------- asm helpers ----------------
__device__ __forceinline__ uint32_t smem_u32(const void* p) {
    return (uint32_t)__cvta_generic_to_shared(p);
}
__device__ __forceinline__ void ldsm_x4(uint32_t r[4], uint32_t addr) {
    asm volatile("ldmatrix.sync.aligned.m8n8.x4.shared.b16 {%0,%1,%2,%3}, [%4];"
        : "=r"(r[0]), "=r"(r[1]), "=r"(r[2]), "=r"(r[3]) : "r"(addr));
}
__device__ __forceinline__ void ldsm_x4_t(uint32_t r[4], uint32_t addr) {
    asm volatile("ldmatrix.sync.aligned.m8n8.x4.trans.shared.b16 {%0,%1,%2,%3}, [%4];"
        : "=r"(r[0]), "=r"(r[1]), "=r"(r[2]), "=r"(r[3]) : "r"(addr));
}
__device__ __forceinline__ void mma16816(float c[4], const uint32_t a0, const uint32_t a1,
                                         const uint32_t a2, const uint32_t a3,
                                         const uint32_t b0, const uint32_t b1) {
    asm volatile("mma.sync.aligned.m16n8k16.row.col.f32.f16.f16.f32 "
        "{%0,%1,%2,%3}, {%4,%5,%6,%7}, {%8,%9}, {%0,%1,%2,%3};"
        : "+f"(c[0]), "+f"(c[1]), "+f"(c[2]), "+f"(c[3])
        : "r"(a0), "r"(a1), "r"(a2), "r"(a3), "r"(b0), "r"(b1));
}
__device__ __forceinline__ uint32_t pack_h2(float x, float y) {
    __half2 h = __floats2half2_rn(x, y);
    return *reinterpret_cast<uint32_t*>(&h);
}
__device__ __forceinline__ void cp16(uint32_t dst, const void* src) {
    asm volatile("cp.async.cg.shared.global [%0], [%1], 16;" :: "r"(dst), "l"(src));
}
__device__ __forceinline__ void cp_commit() { asm volatile("cp.async.commit_group;"); }
__device__ __forceinline__ void cp_wait1()  { asm volatile("cp.async.wait_group 1;"); }
__device__ __forceinline__ void cp_wait0()  { asm volatile("cp.async.wait_group 0;"); }

// exp(s * 0.125) for |s| <= ~1.05 via cubic Horner (coeffs absorb the /8).
__device__ __forceinline__ float exp8(float s) {
    float p = fmaf(s, 3.2552083e-4f, 0.0078125f);
    p = fmaf(p, s, 0.125f);
    return fmaf(p, s, 1.0f);
}

// ---------------- merged prep: x-hi | W_qs-hi | W_out-hi/lo | v-scatter ----------------
__global__ __launch_bounds__(256)
void prep_kernel(const float* __restrict__ x, const float* __restrict__ W_qs,
                 const float* __restrict__ W_out)
{
    const int NX = LSEQ * NDIM;
    const int NW1 = NDIM * QSD;
    const int NWO = NDIM * NDIM;
    int i = blockIdx.x * 256 + threadIdx.x;
    if (i < NX) {
        float v = x[i];
        g_xh[i] = __float2half_rn(v);
        // v-scatter into head-major layout (depends only on x)
        int row = i >> 9, c = i & 511;
        int h = c >> 6, d = c & 63;
        g_v[((size_t)(h * LSEQ + row)) * HDIM + d] = __float2half_rn(v);
    } else if (i < NX + NW1) {
        int j = i - NX;
        g_w1h[j] = __float2half_rn(W_qs[j]);
    } else if (i < NX + NW1 + NWO) {
        int j = i - NX - NW1;
        float v = W_out[j];
        __half h = __float2half_rn(v);
        g_woh[j] = h;
        g_wol[j] = __float2half_rn(v - __half2float(h));
    }
}

// ---------------- 8-warp HMMA GEMM: CTA 128x128, 1-term (for gemm1) ----------------
#define GLD 72
#define BLD 136

__global__ __launch_bounds__(256)
void hmma_gemm_8w(const __half* __restrict__ Ah,
                  const __half* __restrict__ Bh,
                  const float* __restrict__ bias, float* __restrict__ C,
                  int N, int K)
{
    extern __shared__ __half gsm8[];
    const uint32_t sbase = smem_u32(gsm8);

    constexpr int ST_A  = 0;
    constexpr int ST_B  = 128 * GLD;            // 9216 halves
    constexpr int STAGE = 128 * GLD + 64 * BLD; // 17920 halves

    const int tid  = threadIdx.x;
    const int warp = tid >> 5;
    const int lane = tid & 31;
    const int wm = (warp & 3) * 32;
    const int wn = (warp >> 2) * 64;
    const int m0 = blockIdx.y << 7, n0 = blockIdx.x << 7;
    const int KT = K >> 6;

    float acc[2][8][4] = {};

    auto load_stage = [&](int st, int k0) {
        uint32_t sb = sbase + st * STAGE * 2;
        // A: 128 rows x 64 halves
        #pragma unroll 4
        for (int i = tid; i < 128 * 8; i += 256) {
            int r = i >> 3, c = (i & 7) << 3;
            cp16(sb + (ST_A + r * GLD + c) * 2, Ah + (size_t)(m0 + r) * K + k0 + c);
        }
        // B: 64 k-rows x 128 halves
        #pragma unroll 4
        for (int i = tid; i < 64 * 16; i += 256) {
            int r = i >> 4, c = (i & 15) << 3;
            cp16(sb + (ST_B + r * BLD + c) * 2, Bh + (size_t)(k0 + r) * N + n0 + c);
        }
    };

    load_stage(0, 0);
    cp_commit();

    for (int t = 0; t < KT; ++t) {
        if (t + 1 < KT) {
            load_stage((t + 1) & 1, (t + 1) << 6);
            cp_commit();
            cp_wait1();
        } else {
            cp_wait0();
        }
        __syncthreads();

        const uint32_t sb = sbase + (t & 1) * STAGE * 2;

        #pragma unroll
        for (int sp2 = 0; sp2 < 2; ++sp2) {
            uint32_t ah[2][2][4];
            #pragma unroll
            for (int rb = 0; rb < 2; ++rb) {
                int abase = (wm + rb * 16 + (lane & 15)) * GLD
                            + sp2 * 32 + ((lane >> 4) << 3);
                ldsm_x4(ah[rb][0], sb + (ST_A + abase) * 2);
                ldsm_x4(ah[rb][1], sb + (ST_A + abase + 16) * 2);
            }
            const int brow = sp2 * 32 + ((lane >> 3) << 3) + (lane & 7);
            #pragma unroll
            for (int nt = 0; nt < 8; ++nt) {
                uint32_t bh[4];
                ldsm_x4_t(bh, sb + (ST_B + brow * BLD + wn + nt * 8) * 2);
                #pragma unroll
                for (int rb = 0; rb < 2; ++rb) {
                    mma16816(acc[rb][nt], ah[rb][0][0], ah[rb][0][1], ah[rb][0][2], ah[rb][0][3], bh[0], bh[1]);
                    mma16816(acc[rb][nt], ah[rb][1][0], ah[rb][1][1], ah[rb][1][2], ah[rb][1][3], bh[2], bh[3]);
                }
            }
        }
        __syncthreads();
    }

    const int g   = lane >> 2;
    const int tig = lane & 3;
    #pragma unroll
    for (int rb = 0; rb < 2; ++rb) {
        int row0 = m0 + wm + rb * 16 + g;
        #pragma unroll
        for (int nt = 0; nt < 8; ++nt) {
            int col = n0 + wn + nt * 8 + tig * 2;
            C[(size_t)row0 * N + col]           = acc[rb][nt][0] + bias[col];
            C[(size_t)row0 * N + col + 1]       = acc[rb][nt][1] + bias[col + 1];
            C[(size_t)(row0 + 8) * N + col]     = acc[rb][nt][2] + bias[col];
            C[(size_t)(row0 + 8) * N + col + 1] = acc[rb][nt][3] + bias[col + 1];
        }
    }
}

// ---------------- 4-warp HMMA GEMM, 2-term (for gemm4; R13-proven) ----------------
#define BSTR 72

__global__ __launch_bounds__(128)
void hmma_gemm2(const __half* __restrict__ Ah,
                const __half* __restrict__ Bh, const __half* __restrict__ Bl,
                const float* __restrict__ bias, float* __restrict__ C,
                int N, int K)
{
    extern __shared__ __half gsm[];
    const uint32_t sbase = smem_u32(gsm);

    constexpr int A_SZ  = 128 * GLD;
    constexpr int ST_AH = 0;
    constexpr int ST_BH = A_SZ;
    constexpr int ST_BL = A_SZ + 64 * BSTR;
    constexpr int STAGE = A_SZ + 2 * 64 * BSTR;

    const int tid  = threadIdx.x;
    const int warp = tid >> 5;
    const int lane = tid & 31;
    const int m0 = blockIdx.y << 7, n0 = blockIdx.x << 6;
    const int KT = K >> 6;

    float acc[2][8][4] = {};

    auto load_stage = [&](int st, int k0) {
        uint32_t sb = sbase + st * STAGE * 2;
        #pragma unroll 4
        for (int i = tid; i < 128 * 8; i += 128) {
            int r = i >> 3, c = (i & 7) << 3;
            cp16(sb + (ST_AH + r * GLD + c) * 2, Ah + (size_t)(m0 + r) * K + k0 + c);
        }
        #pragma unroll 4
        for (int i = tid; i < 64 * 8; i += 128) {
            int r = i >> 3, c = (i & 7) << 3;
            cp16(sb + (ST_BH + r * BSTR + c) * 2, Bh + (size_t)(k0 + r) * N + n0 + c);
            cp16(sb + (ST_BL + r * BSTR + c) * 2, Bl + (size_t)(k0 + r) * N + n0 + c);
        }
    };

    load_stage(0, 0);
    cp_commit();

    for (int t = 0; t < KT; ++t) {
        if (t + 1 < KT) {
            load_stage((t + 1) & 1, (t + 1) << 6);
            cp_commit();
            cp_wait1();
        } else {
            cp_wait0();
        }
        __syncthreads();

        const uint32_t sb = sbase + (t & 1) * STAGE * 2;

        #pragma unroll
        for (int sp2 = 0; sp2 < 2; ++sp2) {
            uint32_t ah[2][2][4];
            #pragma unroll
            for (int rb = 0; rb < 2; ++rb) {
                int abase = (warp * 32 + rb * 16 + (lane & 15)) * GLD
                            + sp2 * 32 + ((lane >> 4) << 3);
                ldsm_x4(ah[rb][0], sb + (ST_AH + abase) * 2);
                ldsm_x4(ah[rb][1], sb + (ST_AH + abase + 16) * 2);
            }
            const int brow = sp2 * 32 + ((lane >> 3) << 3) + (lane & 7);
            #pragma unroll
            for (int nt = 0; nt < 8; ++nt) {
                uint32_t bh[4], bl[4];
                ldsm_x4_t(bh, sb + (ST_BH + brow * BSTR + nt * 8) * 2);
                ldsm_x4_t(bl, sb + (ST_BL + brow * BSTR + nt * 8) * 2);
                #pragma unroll
                for (int rb = 0; rb < 2; ++rb) {
                    mma16816(acc[rb][nt], ah[rb][0][0], ah[rb][0][1], ah[rb][0][2], ah[rb][0][3], bh[0], bh[1]);
                    mma16816(acc[rb][nt], ah[rb][1][0], ah[rb][1][1], ah[rb][1][2], ah[rb][1][3], bh[2], bh[3]);
                    mma16816(acc[rb][nt], ah[rb][0][0], ah[rb][0][1], ah[rb][0][2], ah[rb][0][3], bl[0], bl[1]);
                    mma16816(acc[rb][nt], ah[rb][1][0], ah[rb][1][1], ah[rb][1][2], ah[rb][1][3], bl[2], bl[3]);
                }
            }
        }
        __syncthreads();
    }

    const int g   = lane >> 2;
    const int tig = lane & 3;
    #pragma unroll
    for (int rb = 0; rb < 2; ++rb) {
        int row0 = m0 + warp * 32 + rb * 16 + g;
        #pragma unroll
        for (int nt = 0; nt < 8; ++nt) {
            int col = n0 + nt * 8 + tig * 2;
            C[(size_t)row0 * N + col]           = acc[rb][nt][0] + bias[col];
            C[(size_t)row0 * N + col + 1]       = acc[rb][nt][1] + bias[col + 1];
            C[(size_t)(row0 + 8) * N + col]     = acc[rb][nt][2] + bias[col];
            C[(size_t)(row0 + 8) * N + col + 1] = acc[rb][nt][3] + bias[col + 1];
        }
    }
}

// ---------------- LN + activations + features (R13-proven, v-scatter removed) ----------------
__global__ __launch_bounds__(256)
void ln_feat_kernel(const float* __restrict__ ln_w, const float* __restrict__ ln_b,
                    const float* __restrict__ freq, const float* __restrict__ shift)
{
    const int i = blockIdx.x;
    const int tid = threadIdx.x;
    const int lane = tid & 31, warp = tid >> 5;
    __shared__ float sh[QSD];
    __shared__ float redA[8], redB[8];
    __shared__ float bcast[2];

    float4 v = reinterpret_cast<const float4*>(g_qs + (size_t)i * QSD)[tid];
    reinterpret_cast<float4*>(sh)[tid] = v;
    float s  = v.x + v.y + v.z + v.w;
    float s2 = v.x * v.x + v.y * v.y + v.z * v.z + v.w * v.w;
    #pragma unroll
    for (int o = 16; o; o >>= 1) {
        s  += __shfl_xor_sync(0xffffffffu, s, o);
        s2 += __shfl_xor_sync(0xffffffffu, s2, o);
    }
    if (!lane) { redA[warp] = s; redB[warp] = s2; }
    __syncthreads();
    if (tid == 0) {
        float a = 0.f, b = 0.f;
        #pragma unroll
        for (int w = 0; w < 8; ++w) { a += redA[w]; b += redB[w]; }
        float mean = a * (1.0f / QSD);
        float var  = b * (1.0f / QSD) - mean * mean;
        bcast[0] = mean;
        bcast[1] = rsqrtf(var + 1e-5f);
    }
    __syncthreads();
    const float mean = bcast[0], rstd = bcast[1];

    float a0, a1;
    {
        float2 ap = reinterpret_cast<const float2*>(sh)[tid];
        float2 w  = reinterpret_cast<const float2*>(ln_w)[tid];
        float2 b  = reinterpret_cast<const float2*>(ln_b)[tid];
        float n0 = (ap.x - mean) * rstd * w.x + b.x;
        float n1 = (ap.y - mean) * rstd * w.y + b.y;
        a0 = 1.0f / (1.0f + __expf(-n0));
        a1 = 1.0f / (1.0f + __expf(-n1));
    }
    float sa2 = a0 * a0 + a1 * a1;
    #pragma unroll
    for (int o = 16; o; o >>= 1) sa2 += __shfl_xor_sync(0xffffffffu, sa2, o);
    if (!lane) redA[warp] = sa2;
    __syncthreads();
    if (tid == 0) {
        float t = 0.f;
        #pragma unroll
        for (int w = 0; w < 8; ++w) t += redA[w];
        bcast[0] = 1.0f / (sqrtf(t) + 1e-8f);
    }
    __syncthreads();
    const float rnorm = bcast[0];

    float2 pp = reinterpret_cast<const float2*>(sh + NDIM)[tid];
    float2 pw = reinterpret_cast<const float2*>(ln_w + NDIM)[tid];
    float2 pb = reinterpret_cast<const float2*>(ln_b + NDIM)[tid];
    float z0 = (pp.x - mean) * rstd * pw.x + pb.x;
    float z1 = (pp.y - mean) * rstd * pw.y + pb.y;
    float e0 = __expf(2.0f * z0), e1 = __expf(2.0f * z1);
    float qp0 = ((e0 - 1.0f) / (e0 + 1.0f)) * PI_F;
    float qp1 = ((e1 - 1.0f) / (e1 + 1.0f)) * PI_F;

    const int c0 = tid * 2;
    const int h = c0 >> 6, d = c0 & 63;
    const float f  = freq[h];
    const float sp = shift[h];
    const float qa0 = a0 * rnorm, qa1 = a1 * rnorm;

    float B0 = CSC * f * qp0, B1 = CSC * f * qp1;
    float A0 = B0 + CSC * sp, A1 = B1 + CSC * sp;
    float ca0, sa0, cb0, sb0, ca1, sa1, cb1, sb1;
    __sincosf(A0, &sa0, &ca0); __sincosf(B0, &sb0, &cb0);
    __sincosf(A1, &sa1, &ca1); __sincosf(B1, &sb1, &cb1);

    size_t base = ((size_t)(h * LSEQ + i)) * FD;
    *reinterpret_cast<__half2*>(&g_qf[base + d])      = __floats2half2_rn(qa0 * ca0, qa1 * ca1);
    *reinterpret_cast<__half2*>(&g_qf[base + 64 + d]) = __floats2half2_rn(qa0 * sa0, qa1 * sa1);
    *reinterpret_cast<__half2*>(&g_kf[base + d])      = __floats2half2_rn(qa0 * cb0, qa1 * cb1);
    *reinterpret_cast<__half2*>(&g_kf[base + 64 + d]) = __floats2half2_rn(qa0 * sb0, qa1 * sb1);
}

// ---------------- tensor-core attention (R13-proven: 2-stage + poly exp) ----------------
#define KLD 136
#define VLD 72
#define A_VOFF (64 * KLD)
#define A_STAGE_B ((64 * KLD + 64 * VLD) * 2)

__global__ __launch_bounds__(128, 2)
void attn_kernel()
{
    extern __shared__ __half asmem[];
    const uint32_t sbase = smem_u32(asmem);

    const int h  = blockIdx.y;
    const int q0 = blockIdx.x << 6;
    const int tid  = threadIdx.x;
    const int warp = tid >> 5;
    const int lane = tid & 31;

    {
        const __half* qg = g_qf + ((size_t)(h * LSEQ + q0)) * FD;
        for (int idx = tid; idx < 64 * 16; idx += 128) {
            int r = idx >> 4, c = (idx & 15) << 3;
            *reinterpret_cast<uint4*>(&asmem[r * KLD + c]) =
                *reinterpret_cast<const uint4*>(&qg[(size_t)r * FD + c]);
        }
    }
    __syncthreads();

    uint32_t qf[8][4];
    {
        int row = warp * 16 + (lane & 15);
        int cof = (lane >> 4) << 3;
        #pragma unroll
        for (int ks = 0; ks < 8; ++ks)
            ldsm_x4(qf[ks], sbase + (row * KLD + ks * 16 + cof) * 2);
    }
    __syncthreads();

    auto load_tile = [&](int st, int k0) {
        uint32_t sb = sbase + st * A_STAGE_B;
        const __half* kg = g_kf + ((size_t)(h * LSEQ + k0)) * FD;
        const __half* vg = g_v  + ((size_t)(h * LSEQ + k0)) * HDIM;
        #pragma unroll 4
        for (int i = tid; i < 64 * 16; i += 128) {
            int r = i >> 4, c = (i & 15) << 3;
            cp16(sb + (r * KLD + c) * 2, kg + (size_t)r * FD + c);
        }
        #pragma unroll 2
        for (int i = tid; i < 64 * 8; i += 128) {
            int r = i >> 3, c = (i & 7) << 3;
            cp16(sb + (A_VOFF + r * VLD + c) * 2, vg + (size_t)r * HDIM + c);
        }
    };

    float oacc[8][4] = {};
    float rl0 = 0.f, rl1 = 0.f;

    load_tile(0, 0);
    cp_commit();

    const int NT = LSEQ / 64;
    for (int kt = 0; kt < NT; ++kt) {
        if (kt + 1 < NT) {
            load_tile((kt + 1) & 1, (kt + 1) << 6);
            cp_commit();
            cp_wait1();
        } else {
            cp_wait0();
        }
        __syncthreads();

        const uint32_t sb = sbase + (kt & 1) * A_STAGE_B;

        float sacc[8][4] = {};
        #pragma unroll
        for (int sp = 0; sp < 4; ++sp) {
            #pragma unroll
            for (int nt = 0; nt < 8; ++nt) {
                uint32_t kf[4];
                ldsm_x4(kf, sb + ((nt * 8 + (lane & 7)) * KLD
                                  + sp * 32 + ((lane >> 3) << 3)) * 2);
                mma16816(sacc[nt], qf[2 * sp][0], qf[2 * sp][1], qf[2 * sp][2], qf[2 * sp][3],
                         kf[0], kf[1]);
                mma16816(sacc[nt], qf[2 * sp + 1][0], qf[2 * sp + 1][1],
                         qf[2 * sp + 1][2], qf[2 * sp + 1][3], kf[2], kf[3]);
            }
        }

        uint32_t pf[8][2];
        #pragma unroll
        for (int nt = 0; nt < 8; ++nt) {
            float e0 = exp8(sacc[nt][0]);
            float e1 = exp8(sacc[nt][1]);
            float e2 = exp8(sacc[nt][2]);
            float e3 = exp8(sacc[nt][3]);
            rl0 += e0 + e1;
            rl1 += e2 + e3;
            pf[nt][0] = pack_h2(e0, e1);
            pf[nt][1] = pack_h2(e2, e3);
        }

        #pragma unroll
        for (int sp = 0; sp < 2; ++sp) {
            int vrow = sp * 32 + ((lane >> 3) << 3) + (lane & 7);
            #pragma unroll
            for (int nt = 0; nt < 8; ++nt) {
                uint32_t vf[4];
                ldsm_x4_t(vf, sb + (A_VOFF + vrow * VLD + nt * 8) * 2);
                mma16816(oacc[nt], pf[4 * sp][0], pf[4 * sp][1],
                         pf[4 * sp + 1][0], pf[4 * sp + 1][1], vf[0], vf[1]);
                mma16816(oacc[nt], pf[4 * sp + 2][0], pf[4 * sp + 2][1],
                         pf[4 * sp + 3][0], pf[4 * sp + 3][1], vf[2], vf[3]);
            }
        }
        __syncthreads();
    }

    rl0 += __shfl_xor_sync(0xffffffffu, rl0, 1);
    rl0 += __shfl_xor_sync(0xffffffffu, rl0, 2);
    rl1 += __shfl_xor_sync(0xffffffffu, rl1, 1);
    rl1 += __shfl_xor_sync(0xffffffffu, rl1, 2);
    const float inv0 = 1.0f / rl0;
    const float inv1 = 1.0f / rl1;

    const int g   = lane >> 2;
    const int tig = lane & 3;
    const int row0 = q0 + warp * 16 + g;
    #pragma unroll
    for (int nt = 0; nt < 8; ++nt) {
        int col = h * HDIM + nt * 8 + tig * 2;
        *reinterpret_cast<__half2*>(&g_aoh[(size_t)row0 * NDIM + col]) =
            __floats2half2_rn(oacc[nt][0] * inv0, oacc[nt][1] * inv0);
        *reinterpret_cast<__half2*>(&g_aoh[(size_t)(row0 + 8) * NDIM + col]) =
            __floats2half2_rn(oacc[nt][2] * inv1, oacc[nt][3] * inv1);
    }
}

// ---------------- launch ----------------
extern "C" void kernel_launch(void* const* d_in, const int* in_sizes, int n_in,
                              void* d_out, int out_size)
{
    const float* x     = (const float*)d_in[0];
    const float* W_qs  = (const float*)d_in[1];
    const float* b_qs  = (const float*)d_in[2];
    const float* ln_w  = (const float*)d_in[3];
    const float* ln_b  = (const float*)d_in[4];
    const float* freq  = (const float*)d_in[5];
    const float* phs   = (const float*)d_in[6];
    const float* W_out = (const float*)d_in[7];
    const float* b_out = (const float*)d_in[8];
    float* out = (float*)d_out;

    void *p_qs, *p_xh, *p_w1h, *p_woh, *p_wol, *p_aoh;
    cudaGetSymbolAddress(&p_qs, g_qs);
    cudaGetSymbolAddress(&p_xh, g_xh);
    cudaGetSymbolAddress(&p_w1h, g_w1h);
    cudaGetSymbolAddress(&p_woh, g_woh); cudaGetSymbolAddress(&p_wol, g_wol);
    cudaGetSymbolAddress(&p_aoh, g_aoh);

    const int smem_g8 = 2 * (128 * GLD + 64 * BLD) * 2;        // 71680
    const int smem_g2 = 2 * (128 * GLD + 2 * 64 * BSTR) * 2;   // 73728
    const int attn_smem = 2 * A_STAGE_B;                       // 53248
    cudaFuncSetAttribute(hmma_gemm_8w, cudaFuncAttributeMaxDynamicSharedMemorySize, smem_g8);
    cudaFuncSetAttribute(hmma_gemm2,   cudaFuncAttributeMaxDynamicSharedMemorySize, smem_g2);
    cudaFuncSetAttribute(attn_kernel,  cudaFuncAttributeMaxDynamicSharedMemorySize, attn_smem);

    // 0) merged prep (includes v-scatter)
    const int NPREP = LSEQ * NDIM + NDIM * QSD + NDIM * NDIM;
    prep_kernel<<<(NPREP + 255) / 256, 256>>>(x, W_qs, W_out);

    // 1) qs = x @ W_qs + b_qs (fp16, 8-warp 128x128 tiles)
    hmma_gemm_8w<<<dim3(QSD / 128, LSEQ / 128), 256, smem_g8>>>(
        (const __half*)p_xh, (const __half*)p_w1h,
        b_qs, (float*)p_qs, QSD, NDIM);
    // 2) LN + activations + features
    ln_feat_kernel<<<LSEQ, 256>>>(ln_w, ln_b, freq, phs);
    // 3) attention
    attn_kernel<<<dim3(LSEQ / 64, NHEAD), 128, attn_smem>>>();
    // 4) out = AO @ W_out + b_out (2-term)
    hmma_gemm2<<<dim3(NDIM / 64, LSEQ / 128), 128, smem_g2>>>(
        (const __half*)p_aoh,
        (const __half*)p_woh, (const __half*)p_wol,
        b_out, out, NDIM, NDIM);
}

// round 16
// speedup vs baseline: 1.1047x; 1.0532x over previous
#include <cuda_runtime.h>
#include <cuda_fp16.h>
#include <cstdint>
#include <math.h>

#define LSEQ 2048
#define NDIM 512
#define NHEAD 8
#define HDIM 64
#define QSD 1024
#define FD 128
#define PI_F 3.14159265358979323846f
#define CSC (1024.0f / 1023.0f)

// ---------------- static device scratch ----------------
__device__ __align__(256) __half g_qsh[LSEQ * QSD];   // qs stored fp16
__device__ __align__(256) __half g_qf[NHEAD * LSEQ * FD];
__device__ __align__(256) __half g_kf[NHEAD * LSEQ * FD];
__device__ __align__(256) __half g_v [NHEAD * LSEQ * HDIM];
__device__ __align__(256) __half g_xh[LSEQ * NDIM];
__device__ __align__(256) __half g_w1h[NDIM * QSD];   // W_qs K-major hi
__device__ __align__(256) __half g_woh[NDIM * NDIM];  // W_out K-major hi
__device__ __align__(256) __half g_aoh[LSEQ * NDIM];

// ---------------- asm helpers ----------------
__device__ __forceinline__ uint32_t smem_u32(const void* p) {
    return (uint32_t)__cvta_generic_to_shared(p);
}
__device__ __forceinline__ void ldsm_x4(uint32_t r[4], uint32_t addr) {
    asm volatile("ldmatrix.sync.aligned.m8n8.x4.shared.b16 {%0,%1,%2,%3}, [%4];"
        : "=r"(r[0]), "=r"(r[1]), "=r"(r[2]), "=r"(r[3]) : "r"(addr));
}
__device__ __forceinline__ void ldsm_x4_t(uint32_t r[4], uint32_t addr) {
    asm volatile("ldmatrix.sync.aligned.m8n8.x4.trans.shared.b16 {%0,%1,%2,%3}, [%4];"
        : "=r"(r[0]), "=r"(r[1]), "=r"(r[2]), "=r"(r[3]) : "r"(addr));
}
__device__ __forceinline__ void mma16816(float c[4], const uint32_t a0, const uint32_t a1,
                                         const uint32_t a2, const uint32_t a3,
                                         const uint32_t b0, const uint32_t b1) {
    asm volatile("mma.sync.aligned.m16n8k16.row.col.f32.f16.f16.f32 "
        "{%0,%1,%2,%3}, {%4,%5,%6,%7}, {%8,%9}, {%0,%1,%2,%3};"
        : "+f"(c[0]), "+f"(c[1]), "+f"(c[2]), "+f"(c[3])
        : "r"(a0), "r"(a1), "r"(a2), "r"(a3), "r"(b0), "r"(b1));
}
__device__ __forceinline__ uint32_t pack_h2(float x, float y) {
    __half2 h = __floats2half2_rn(x, y);
    return *reinterpret_cast<uint32_t*>(&h);
}
__device__ __forceinline__ void cp16(uint32_t dst, const void* src) {
    asm volatile("cp.async.cg.shared.global [%0], [%1], 16;" :: "r"(dst), "l"(src));
}
__device__ __forceinline__ void cp_commit() { asm volatile("cp.async.commit_group;"); }
__device__ __forceinline__ void cp_wait1()  { asm volatile("cp.async.wait_group 1;"); }
__device__ __forceinline__ void cp_wait0()  { asm volatile("cp.async.wait_group 0;"); }

// exp(s * 0.125) for |s| <= ~1.05 via cubic Horner (coeffs absorb the /8).
__device__ __forceinline__ float exp8(float s) {
    float p = fmaf(s, 3.2552083e-4f, 0.0078125f);
    p = fmaf(p, s, 0.125f);
    return fmaf(p, s, 1.0f);
}

// ---------------- merged prep (vectorized x4): x-hi + v-scatter | W_qs-hi | W_out-hi ----------------
__global__ __launch_bounds__(256)
void prep_kernel(const float* __restrict__ x, const float* __restrict__ W_qs,
                 const float* __restrict__ W_out)
{
    const int NX = LSEQ * NDIM;          // /4 = 262144
    const int NW1 = NDIM * QSD;          // /4 = 131072
    const int NWO = NDIM * NDIM;         // /4 = 65536
    int q = blockIdx.x * 256 + threadIdx.x;   // quad index
    if (q < NX / 4) {
        int i = q * 4;
        float4 v = *reinterpret_cast<const float4*>(&x[i]);
        __half2 h01 = __floats2half2_rn(v.x, v.y);
        __half2 h23 = __floats2half2_rn(v.z, v.w);
        *reinterpret_cast<__half2*>(&g_xh[i])     = h01;
        *reinterpret_cast<__half2*>(&g_xh[i + 2]) = h23;
        // v-scatter (same 4 consecutive d within one head)
        int row = i >> 9, c = i & 511;
        int h = c >> 6, d = c & 63;
        __half* vp = &g_v[((size_t)(h * LSEQ + row)) * HDIM + d];
        *reinterpret_cast<__half2*>(vp)     = h01;
        *reinterpret_cast<__half2*>(vp + 2) = h23;
    } else if (q < (NX + NW1) / 4) {
        int j = q * 4 - NX;
        float4 v = *reinterpret_cast<const float4*>(&W_qs[j]);
        *reinterpret_cast<__half2*>(&g_w1h[j])     = __floats2half2_rn(v.x, v.y);
        *reinterpret_cast<__half2*>(&g_w1h[j + 2]) = __floats2half2_rn(v.z, v.w);
    } else if (q < (NX + NW1 + NWO) / 4) {
        int j = q * 4 - NX - NW1;
        float4 v = *reinterpret_cast<const float4*>(&W_out[j]);
        *reinterpret_cast<__half2*>(&g_woh[j])     = __floats2half2_rn(v.x, v.y);
        *reinterpret_cast<__half2*>(&g_woh[j + 2]) = __floats2half2_rn(v.z, v.w);
    }
}

// ---------------- 8-warp HMMA GEMM: CTA 128x128, 1-term, fp16 C out (gemm1) ----------------
#define GLD 72
#define BLD 136

__global__ __launch_bounds__(256)
void hmma_gemm_8w(const __half* __restrict__ Ah,
                  const __half* __restrict__ Bh,
                  const float* __restrict__ bias, __half* __restrict__ C,
                  int N, int K)
{
    extern __shared__ __half gsm8[];
    const uint32_t sbase = smem_u32(gsm8);

    constexpr int ST_A  = 0;
    constexpr int ST_B  = 128 * GLD;
    constexpr int STAGE = 128 * GLD + 64 * BLD;

    const int tid  = threadIdx.x;
    const int warp = tid >> 5;
    const int lane = tid & 31;
    const int wm = (warp & 3) * 32;
    const int wn = (warp >> 2) * 64;
    const int m0 = blockIdx.y << 7, n0 = blockIdx.x << 7;
    const int KT = K >> 6;

    float acc[2][8][4] = {};

    auto load_stage = [&](int st, int k0) {
        uint32_t sb = sbase + st * STAGE * 2;
        #pragma unroll 4
        for (int i = tid; i < 128 * 8; i += 256) {
            int r = i >> 3, c = (i & 7) << 3;
            cp16(sb + (ST_A + r * GLD + c) * 2, Ah + (size_t)(m0 + r) * K + k0 + c);
        }
        #pragma unroll 4
        for (int i = tid; i < 64 * 16; i += 256) {
            int r = i >> 4, c = (i & 15) << 3;
            cp16(sb + (ST_B + r * BLD + c) * 2, Bh + (size_t)(k0 + r) * N + n0 + c);
        }
    };

    load_stage(0, 0);
    cp_commit();

    for (int t = 0; t < KT; ++t) {
        if (t + 1 < KT) {
            load_stage((t + 1) & 1, (t + 1) << 6);
            cp_commit();
            cp_wait1();
        } else {
            cp_wait0();
        }
        __syncthreads();

        const uint32_t sb = sbase + (t & 1) * STAGE * 2;

        #pragma unroll
        for (int sp2 = 0; sp2 < 2; ++sp2) {
            uint32_t ah[2][2][4];
            #pragma unroll
            for (int rb = 0; rb < 2; ++rb) {
                int abase = (wm + rb * 16 + (lane & 15)) * GLD
                            + sp2 * 32 + ((lane >> 4) << 3);
                ldsm_x4(ah[rb][0], sb + (ST_A + abase) * 2);
                ldsm_x4(ah[rb][1], sb + (ST_A + abase + 16) * 2);
            }
            const int brow = sp2 * 32 + ((lane >> 3) << 3) + (lane & 7);
            #pragma unroll
            for (int nt = 0; nt < 8; ++nt) {
                uint32_t bh[4];
                ldsm_x4_t(bh, sb + (ST_B + brow * BLD + wn + nt * 8) * 2);
                #pragma unroll
                for (int rb = 0; rb < 2; ++rb) {
                    mma16816(acc[rb][nt], ah[rb][0][0], ah[rb][0][1], ah[rb][0][2], ah[rb][0][3], bh[0], bh[1]);
                    mma16816(acc[rb][nt], ah[rb][1][0], ah[rb][1][1], ah[rb][1][2], ah[rb][1][3], bh[2], bh[3]);
                }
            }
        }
        __syncthreads();
    }

    const int g   = lane >> 2;
    const int tig = lane & 3;
    #pragma unroll
    for (int rb = 0; rb < 2; ++rb) {
        int row0 = m0 + wm + rb * 16 + g;
        #pragma unroll
        for (int nt = 0; nt < 8; ++nt) {
            int col = n0 + wn + nt * 8 + tig * 2;
            *reinterpret_cast<__half2*>(&C[(size_t)row0 * N + col]) =
                __floats2half2_rn(acc[rb][nt][0] + bias[col], acc[rb][nt][1] + bias[col + 1]);
            *reinterpret_cast<__half2*>(&C[(size_t)(row0 + 8) * N + col]) =
                __floats2half2_rn(acc[rb][nt][2] + bias[col], acc[rb][nt][3] + bias[col + 1]);
        }
    }
}

// ---------------- 4-warp HMMA GEMM, 1-term fp16, f32 out (gemm4) ----------------
#define BSTR 72

__global__ __launch_bounds__(128)
void hmma_gemm1(const __half* __restrict__ Ah,
                const __half* __restrict__ Bh,
                const float* __restrict__ bias, float* __restrict__ C,
                int N, int K)
{
    extern __shared__ __half gsm[];
    const uint32_t sbase = smem_u32(gsm);

    constexpr int A_SZ  = 128 * GLD;
    constexpr int ST_AH = 0;
    constexpr int ST_BH = A_SZ;
    constexpr int STAGE = A_SZ + 64 * BSTR;

    const int tid  = threadIdx.x;
    const int warp = tid >> 5;
    const int lane = tid & 31;
    const int m0 = blockIdx.y << 7, n0 = blockIdx.x << 6;
    const int KT = K >> 6;

    float acc[2][8][4] = {};

    auto load_stage = [&](int st, int k0) {
        uint32_t sb = sbase + st * STAGE * 2;
        #pragma unroll 4
        for (int i = tid; i < 128 * 8; i += 128) {
            int r = i >> 3, c = (i & 7) << 3;
            cp16(sb + (ST_AH + r * GLD + c) * 2, Ah + (size_t)(m0 + r) * K + k0 + c);
        }
        #pragma unroll 4
        for (int i = tid; i < 64 * 8; i += 128) {
            int r = i >> 3, c = (i & 7) << 3;
            cp16(sb + (ST_BH + r * BSTR + c) * 2, Bh + (size_t)(k0 + r) * N + n0 + c);
        }
    };

    load_stage(0, 0);
    cp_commit();

    for (int t = 0; t < KT; ++t) {
        if (t + 1 < KT) {
            load_stage((t + 1) & 1, (t + 1) << 6);
            cp_commit();
            cp_wait1();
        } else {
            cp_wait0();
        }
        __syncthreads();

        const uint32_t sb = sbase + (t & 1) * STAGE * 2;

        #pragma unroll
        for (int sp2 = 0; sp2 < 2; ++sp2) {
            uint32_t ah[2][2][4];
            #pragma unroll
            for (int rb = 0; rb < 2; ++rb) {
                int abase = (warp * 32 + rb * 16 + (lane & 15)) * GLD
                            + sp2 * 32 + ((lane >> 4) << 3);
                ldsm_x4(ah[rb][0], sb + (ST_AH + abase) * 2);
                ldsm_x4(ah[rb][1], sb + (ST_AH + abase + 16) * 2);
            }
            const int brow = sp2 * 32 + ((lane >> 3) << 3) + (lane & 7);
            #pragma unroll
            for (int nt = 0; nt < 8; ++nt) {
                uint32_t bh[4];
                ldsm_x4_t(bh, sb + (ST_BH + brow * BSTR + nt * 8) * 2);
                #pragma unroll
                for (int rb = 0; rb < 2; ++rb) {
                    mma16816(acc[rb][nt], ah[rb][0][0], ah[rb][0][1], ah[rb][0][2], ah[rb][0][3], bh[0], bh[1]);
                    mma16816(acc[rb][nt], ah[rb][1][0], ah[rb][1][1], ah[rb][1][2], ah[rb][1][3], bh[2], bh[3]);
                }
            }
        }
        __syncthreads();
    }

    const int g   = lane >> 2;
    const int tig = lane & 3;
    #pragma unroll
    for (int rb = 0; rb < 2; ++rb) {
        int row0 = m0 + warp * 32 + rb * 16 + g;
        #pragma unroll
        for (int nt = 0; nt < 8; ++nt) {
            int col = n0 + nt * 8 + tig * 2;
            C[(size_t)row0 * N + col]           = acc[rb][nt][0] + bias[col];
            C[(size_t)row0 * N + col + 1]       = acc[rb][nt][1] + bias[col + 1];
            C[(size_t)(row0 + 8) * N + col]     = acc[rb][nt][2] + bias[col];
            C[(size_t)(row0 + 8) * N + col + 1] = acc[rb][nt][3] + bias[col + 1];
        }
    }
}

// ---------------- LN + activations + features (fp16 qs in) ----------------
__global__ __launch_bounds__(256)
void ln_feat_kernel(const float* __restrict__ ln_w, const float* __restrict__ ln_b,
                    const float* __restrict__ freq, const float* __restrict__ shift)
{
    const int i = blockIdx.x;
    const int tid = threadIdx.x;
    const int lane = tid & 31, warp = tid >> 5;
    __shared__ float sh[QSD];
    __shared__ float redA[8], redB[8];
    __shared__ float bcast[2];

    const __half2* row = reinterpret_cast<const __half2*>(g_qsh + (size_t)i * QSD);
    float2 v01 = __half22float2(row[2 * tid]);
    float2 v23 = __half22float2(row[2 * tid + 1]);
    sh[4 * tid + 0] = v01.x; sh[4 * tid + 1] = v01.y;
    sh[4 * tid + 2] = v23.x; sh[4 * tid + 3] = v23.y;
    float s  = v01.x + v01.y + v23.x + v23.y;
    float s2 = v01.x * v01.x + v01.y * v01.y + v23.x * v23.x + v23.y * v23.y;
    #pragma unroll
    for (int o = 16; o; o >>= 1) {
        s  += __shfl_xor_sync(0xffffffffu, s, o);
        s2 += __shfl_xor_sync(0xffffffffu, s2, o);
    }
    if (!lane) { redA[warp] = s; redB[warp] = s2; }
    __syncthreads();
    if (tid == 0) {
        float a = 0.f, b = 0.f;
        #pragma unroll
        for (int w = 0; w < 8; ++w) { a += redA[w]; b += redB[w]; }
        float mean = a * (1.0f / QSD);
        float var  = b * (1.0f / QSD) - mean * mean;
        bcast[0] = mean;
        bcast[1] = rsqrtf(var + 1e-5f);
    }
    __syncthreads();
    const float mean = bcast[0], rstd = bcast[1];

    float a0, a1;
    {
        float2 ap = reinterpret_cast<const float2*>(sh)[tid];
        float2 w  = reinterpret_cast<const float2*>(ln_w)[tid];
        float2 b  = reinterpret_cast<const float2*>(ln_b)[tid];
        float n0 = (ap.x - mean) * rstd * w.x + b.x;
        float n1 = (ap.y - mean) * rstd * w.y + b.y;
        a0 = 1.0f / (1.0f + __expf(-n0));
        a1 = 1.0f / (1.0f + __expf(-n1));
    }
    float sa2 = a0 * a0 + a1 * a1;
    #pragma unroll
    for (int o = 16; o; o >>= 1) sa2 += __shfl_xor_sync(0xffffffffu, sa2, o);
    if (!lane) redA[warp] = sa2;
    __syncthreads();
    if (tid == 0) {
        float t = 0.f;
        #pragma unroll
        for (int w = 0; w < 8; ++w) t += redA[w];
        bcast[0] = 1.0f / (sqrtf(t) + 1e-8f);
    }
    __syncthreads();
    const float rnorm = bcast[0];

    float2 pp = reinterpret_cast<const float2*>(sh + NDIM)[tid];
    float2 pw = reinterpret_cast<const float2*>(ln_w + NDIM)[tid];
    float2 pb = reinterpret_cast<const float2*>(ln_b + NDIM)[tid];
    float z0 = (pp.x - mean) * rstd * pw.x + pb.x;
    float z1 = (pp.y - mean) * rstd * pw.y + pb.y;
    float e0 = __expf(2.0f * z0), e1 = __expf(2.0f * z1);
    float qp0 = ((e0 - 1.0f) / (e0 + 1.0f)) * PI_F;
    float qp1 = ((e1 - 1.0f) / (e1 + 1.0f)) * PI_F;

    const int c0 = tid * 2;
    const int h = c0 >> 6, d = c0 & 63;
    const float f  = freq[h];
    const float sp = shift[h];
    const float qa0 = a0 * rnorm, qa1 = a1 * rnorm;

    float B0 = CSC * f * qp0, B1 = CSC * f * qp1;
    float A0 = B0 + CSC * sp, A1 = B1 + CSC * sp;
    float ca0, sa0, cb0, sb0, ca1, sa1, cb1, sb1;
    __sincosf(A0, &sa0, &ca0); __sincosf(B0, &sb0, &cb0);
    __sincosf(A1, &sa1, &ca1); __sincosf(B1, &sb1, &cb1);

    size_t base = ((size_t)(h * LSEQ + i)) * FD;
    *reinterpret_cast<__half2*>(&g_qf[base + d])      = __floats2half2_rn(qa0 * ca0, qa1 * ca1);
    *reinterpret_cast<__half2*>(&g_qf[base + 64 + d]) = __floats2half2_rn(qa0 * sa0, qa1 * sa1);
    *reinterpret_cast<__half2*>(&g_kf[base + d])      = __floats2half2_rn(qa0 * cb0, qa1 * cb1);
    *reinterpret_cast<__half2*>(&g_kf[base + 64 + d]) = __floats2half2_rn(qa0 * sb0, qa1 * sb1);
}

// ---------------- tensor-core attention (R13/R15-proven) ----------------
#define KLD 136
#define VLD 72
#define A_VOFF (64 * KLD)
#define A_STAGE_B ((64 * KLD + 64 * VLD) * 2)

__global__ __launch_bounds__(128, 2)
void attn_kernel()
{
    extern __shared__ __half asmem[];
    const uint32_t sbase = smem_u32(asmem);

    const int h  = blockIdx.y;
    const int q0 = blockIdx.x << 6;
    const int tid  = threadIdx.x;
    const int warp = tid >> 5;
    const int lane = tid & 31;

    {
        const __half* qg = g_qf + ((size_t)(h * LSEQ + q0)) * FD;
        for (int idx = tid; idx < 64 * 16; idx += 128) {
            int r = idx >> 4, c = (idx & 15) << 3;
            *reinterpret_cast<uint4*>(&asmem[r * KLD + c]) =
                *reinterpret_cast<const uint4*>(&qg[(size_t)r * FD + c]);
        }
    }
    __syncthreads();

    uint32_t qf[8][4];
    {
        int row = warp * 16 + (lane & 15);
        int cof = (lane >> 4) << 3;
        #pragma unroll
        for (int ks = 0; ks < 8; ++ks)
            ldsm_x4(qf[ks], sbase + (row * KLD + ks * 16 + cof) * 2);
    }
    __syncthreads();

    auto load_tile = [&](int st, int k0) {
        uint32_t sb = sbase + st * A_STAGE_B;
        const __half* kg = g_kf + ((size_t)(h * LSEQ + k0)) * FD;
        const __half* vg = g_v  + ((size_t)(h * LSEQ + k0)) * HDIM;
        #pragma unroll 4
        for (int i = tid; i < 64 * 16; i += 128) {
            int r = i >> 4, c = (i & 15) << 3;
            cp16(sb + (r * KLD + c) * 2, kg + (size_t)r * FD + c);
        }
        #pragma unroll 2
        for (int i = tid; i < 64 * 8; i += 128) {
            int r = i >> 3, c = (i & 7) << 3;
            cp16(sb + (A_VOFF + r * VLD + c) * 2, vg + (size_t)r * HDIM + c);
        }
    };

    float oacc[8][4] = {};
    float rl0 = 0.f, rl1 = 0.f;

    load_tile(0, 0);
    cp_commit();

    const int NT = LSEQ / 64;
    for (int kt = 0; kt < NT; ++kt) {
        if (kt + 1 < NT) {
            load_tile((kt + 1) & 1, (kt + 1) << 6);
            cp_commit();
            cp_wait1();
        } else {
            cp_wait0();
        }
        __syncthreads();

        const uint32_t sb = sbase + (kt & 1) * A_STAGE_B;

        float sacc[8][4] = {};
        #pragma unroll
        for (int sp = 0; sp < 4; ++sp) {
            #pragma unroll
            for (int nt = 0; nt < 8; ++nt) {
                uint32_t kf[4];
                ldsm_x4(kf, sb + ((nt * 8 + (lane & 7)) * KLD
                                  + sp * 32 + ((lane >> 3) << 3)) * 2);
                mma16816(sacc[nt], qf[2 * sp][0], qf[2 * sp][1], qf[2 * sp][2], qf[2 * sp][3],
                         kf[0], kf[1]);
                mma16816(sacc[nt], qf[2 * sp + 1][0], qf[2 * sp + 1][1],
                         qf[2 * sp + 1][2], qf[2 * sp + 1][3], kf[2], kf[3]);
            }
        }

        uint32_t pf[8][2];
        #pragma unroll
        for (int nt = 0; nt < 8; ++nt) {
            float e0 = exp8(sacc[nt][0]);
            float e1 = exp8(sacc[nt][1]);
            float e2 = exp8(sacc[nt][2]);
            float e3 = exp8(sacc[nt][3]);
            rl0 += e0 + e1;
            rl1 += e2 + e3;
            pf[nt][0] = pack_h2(e0, e1);
            pf[nt][1] = pack_h2(e2, e3);
        }

        #pragma unroll
        for (int sp = 0; sp < 2; ++sp) {
            int vrow = sp * 32 + ((lane >> 3) << 3) + (lane & 7);
            #pragma unroll
            for (int nt = 0; nt < 8; ++nt) {
                uint32_t vf[4];
                ldsm_x4_t(vf, sb + (A_VOFF + vrow * VLD + nt * 8) * 2);
                mma16816(oacc[nt], pf[4 * sp][0], pf[4 * sp][1],
                         pf[4 * sp + 1][0], pf[4 * sp + 1][1], vf[0], vf[1]);
                mma16816(oacc[nt], pf[4 * sp + 2][0], pf[4 * sp + 2][1],
                         pf[4 * sp + 3][0], pf[4 * sp + 3][1], vf[2], vf[3]);
            }
        }
        __syncthreads();
    }

    rl0 += __shfl_xor_sync(0xffffffffu, rl0, 1);
    rl0 += __shfl_xor_sync(0xffffffffu, rl0, 2);
    rl1 += __shfl_xor_sync(0xffffffffu, rl1, 1);
    rl1 += __shfl_xor_sync(0xffffffffu, rl1, 2);
    const float inv0 = 1.0f / rl0;
    const float inv1 = 1.0f / rl1;

    const int g   = lane >> 2;
    const int tig = lane & 3;
    const int row0 = q0 + warp * 16 + g;
    #pragma unroll
    for (int nt = 0; nt < 8; ++nt) {
        int col = h * HDIM + nt * 8 + tig * 2;
        *reinterpret_cast<__half2*>(&g_aoh[(size_t)row0 * NDIM + col]) =
            __floats2half2_rn(oacc[nt][0] * inv0, oacc[nt][1] * inv0);
        *reinterpret_cast<__half2*>(&g_aoh[(size_t)(row0 + 8) * NDIM + col]) =
            __floats2half2_rn(oacc[nt][2] * inv1, oacc[nt][3] * inv1);
    }
}

// ---------------- launch ----------------
extern "C" void kernel_launch(void* const* d_in, const int* in_sizes, int n_in,
                              void* d_out, int out_size)
{
    const float* x     = (const float*)d_in[0];
    const float* W_qs  = (const float*)d_in[1];
    const float* b_qs  = (const float*)d_in[2];
    const float* ln_w  = (const float*)d_in[3];
    const float* ln_b  = (const float*)d_in[4];
    const float* freq  = (const float*)d_in[5];
    const float* phs   = (const float*)d_in[6];
    const float* W_out = (const float*)d_in[7];
    const float* b_out = (const float*)d_in[8];
    float* out = (float*)d_out;

    void *p_qsh, *p_xh, *p_w1h, *p_woh, *p_aoh;
    cudaGetSymbolAddress(&p_qsh, g_qsh);
    cudaGetSymbolAddress(&p_xh, g_xh);
    cudaGetSymbolAddress(&p_w1h, g_w1h);
    cudaGetSymbolAddress(&p_woh, g_woh);
    cudaGetSymbolAddress(&p_aoh, g_aoh);

    const int smem_g8 = 2 * (128 * GLD + 64 * BLD) * 2;    // 71680
    const int smem_g1 = 2 * (128 * GLD + 64 * BSTR) * 2;   // 55296
    const int attn_smem = 2 * A_STAGE_B;                   // 53248
    cudaFuncSetAttribute(hmma_gemm_8w, cudaFuncAttributeMaxDynamicSharedMemorySize, smem_g8);
    cudaFuncSetAttribute(hmma_gemm1,   cudaFuncAttributeMaxDynamicSharedMemorySize, smem_g1);
    cudaFuncSetAttribute(attn_kernel,  cudaFuncAttributeMaxDynamicSharedMemorySize, attn_smem);

    // 0) merged prep (vectorized)
    const int NPREPQ = (LSEQ * NDIM + NDIM * QSD + NDIM * NDIM) / 4;
    prep_kernel<<<(NPREPQ + 255) / 256, 256>>>(x, W_qs, W_out);

    // 1) qs = x @ W_qs + b_qs (fp16, 8-warp 128x128 tiles, fp16 out)
    hmma_gemm_8w<<<dim3(QSD / 128, LSEQ / 128), 256, smem_g8>>>(
        (const __half*)p_xh, (const __half*)p_w1h,
        b_qs, (__half*)p_qsh, QSD, NDIM);
    // 2) LN + activations + features (reads fp16 qs)
    ln_feat_kernel<<<LSEQ, 256>>>(ln_w, ln_b, freq, phs);
    // 3) attention
    attn_kernel<<<dim3(LSEQ / 64, NHEAD), 128, attn_smem>>>();
    // 4) out = AO @ W_out + b_out (plain fp16)
    hmma_gemm1<<<dim3(NDIM / 64, LSEQ / 128), 128, smem_g1>>>(
        (const __half*)p_aoh, (const __half*)p_woh,
        b_out, out, NDIM, NDIM);
}